// round 2
// baseline (speedup 1.0000x reference)
#include <cuda_runtime.h>
#include <cstdint>

#define D 128
#define D4 32          // D / 4
#define N_MAX 50000
#define NPB 32         // nodes per block in the GEMM kernel
#define LN_EPS 1e-5f

// Scratch: aggregated features (agg = h + sum_{e: dst=n} h[src])
__device__ float g_agg[(size_t)N_MAX * D];

// ---------------------------------------------------------------------------
// Kernel 1: agg = h  (residual pre-load, so scatter can accumulate on top)
// ---------------------------------------------------------------------------
__global__ void k_init_agg(const float4* __restrict__ h4, int n4) {
    int i = blockIdx.x * blockDim.x + threadIdx.x;
    float4* agg4 = reinterpret_cast<float4*>(g_agg);
    if (i < n4) agg4[i] = h4[i];
}

// ---------------------------------------------------------------------------
// Kernel 2: scatter-add  agg[dst[e]] += h[src[e]]   (one warp per edge)
// Each lane owns 4 consecutive floats of the 128-wide row.
// edge_index is int32 (JAX default x64-disabled).
// ---------------------------------------------------------------------------
__global__ void k_scatter(const float* __restrict__ h,
                          const int* __restrict__ src,
                          const int* __restrict__ dst,
                          int E) {
    int warp_id = (blockIdx.x * blockDim.x + threadIdx.x) >> 5;
    int lane = threadIdx.x & 31;
    if (warp_id >= E) return;
    int s = src[warp_id];
    int d = dst[warp_id];
    float4 v = reinterpret_cast<const float4*>(h + (size_t)s * D)[lane];
    float* ap = g_agg + (size_t)d * D + lane * 4;
    atomicAdd(ap + 0, v.x);   // result unused -> REDG.ADD (no return)
    atomicAdd(ap + 1, v.y);
    atomicAdd(ap + 2, v.z);
    atomicAdd(ap + 3, v.w);
}

// ---------------------------------------------------------------------------
// Kernel 3: fused  y = agg @ W^T + b ; LayerNorm ; ReLU
// 128 threads/block. Thread j computes output column j. W row j lives in
// 32 float4 registers. NPB nodes per block; x rows staged in shared.
// LN: warp shuffle reduce -> 4 partials in shared -> each thread finalizes.
// ---------------------------------------------------------------------------
__global__ __launch_bounds__(128)
void k_gemm_ln_relu(const float* __restrict__ W,
                    const float* __restrict__ bias,
                    const float* __restrict__ gamma,
                    const float* __restrict__ beta,
                    float* __restrict__ out,
                    int N) {
    __shared__ float4 xs[NPB][D4];
    __shared__ float red_s[NPB][4];
    __shared__ float red_q[NPB][4];

    const int j = threadIdx.x;          // output column 0..127
    const int lane = j & 31;
    const int warp = j >> 5;
    const int base = blockIdx.x * NPB;

    // Load W row j into registers (32 x float4 = 128 regs). 64KB/block from L2.
    float4 w[D4];
    const float4* W4 = reinterpret_cast<const float4*>(W);
#pragma unroll
    for (int k = 0; k < D4; k++) w[k] = W4[j * D4 + k];

    const float bj  = bias[j];
    const float gj  = gamma[j];
    const float bej = beta[j];

    // Stage NPB rows of agg into shared (coalesced float4 loads)
    const float4* X4 = reinterpret_cast<const float4*>(g_agg) + (size_t)base * D4;
    int valid_rows = N - base;
    if (valid_rows > NPB) valid_rows = NPB;
    for (int i = threadIdx.x; i < NPB * D4; i += 128) {
        int r = i / D4;
        if (r < valid_rows) {
            xs[r][i % D4] = X4[i];
        } else {
            xs[r][i % D4] = make_float4(0.f, 0.f, 0.f, 0.f);
        }
    }
    __syncthreads();

    for (int n = 0; n < NPB; n++) {
        // Dot product: 4 independent accumulator chains
        float y0 = 0.f, y1 = 0.f, y2 = 0.f, y3 = 0.f;
#pragma unroll
        for (int k = 0; k < D4; k++) {
            float4 x4 = xs[n][k];          // broadcast LDS
            y0 += x4.x * w[k].x;
            y1 += x4.y * w[k].y;
            y2 += x4.z * w[k].z;
            y3 += x4.w * w[k].w;
        }
        float y = ((y0 + y1) + (y2 + y3)) + bj;

        // Block reduce (sum, sumsq) over the 128 columns
        float s = y, q = y * y;
#pragma unroll
        for (int o = 16; o > 0; o >>= 1) {
            s += __shfl_xor_sync(0xFFFFFFFFu, s, o);
            q += __shfl_xor_sync(0xFFFFFFFFu, q, o);
        }
        if (lane == 0) { red_s[n][warp] = s; red_q[n][warp] = q; }
        __syncthreads();

        float S = (red_s[n][0] + red_s[n][1]) + (red_s[n][2] + red_s[n][3]);
        float Q = (red_q[n][0] + red_q[n][1]) + (red_q[n][2] + red_q[n][3]);
        float mu  = S * (1.0f / D);
        float var = Q * (1.0f / D) - mu * mu;
        float rs  = rsqrtf(var + LN_EPS);
        float o   = (y - mu) * rs * gj + bej;
        o = fmaxf(o, 0.f);

        if (base + n < N) {
            out[(size_t)(base + n) * D + j] = o;
        }
    }
}

// ---------------------------------------------------------------------------
extern "C" void kernel_launch(void* const* d_in, const int* in_sizes, int n_in,
                              void* d_out, int out_size) {
    const float* h     = (const float*)d_in[0];
    const int*   ei    = (const int*)d_in[1];   // [2, E] int32 (JAX x64 off)
    const float* W     = (const float*)d_in[2];
    const float* bias  = (const float*)d_in[3];
    const float* gamma = (const float*)d_in[4];
    const float* beta  = (const float*)d_in[5];
    float*       out   = (float*)d_out;

    const int N = in_sizes[0] / D;
    const int E = in_sizes[1] / 2;
    const int* src = ei;
    const int* dst = ei + E;

    // 1) agg = h
    int n4 = N * D4;
    k_init_agg<<<(n4 + 255) / 256, 256>>>(reinterpret_cast<const float4*>(h), n4);

    // 2) scatter-add (1 warp per edge, 8 edges per 256-thread block)
    int blocks_sc = (E + 7) / 8;
    k_scatter<<<blocks_sc, 256>>>(h, src, dst, E);

    // 3) fused linear + layernorm + relu
    int blocks_g = (N + NPB - 1) / NPB;
    k_gemm_ln_relu<<<blocks_g, 128>>>(W, bias, gamma, beta, out, N);
}

// round 3
// speedup vs baseline: 1.2162x; 1.2162x over previous
#include <cuda_runtime.h>
#include <cstdint>

#define D 128
#define D4 32          // D / 4
#define N_MAX 50000
#define E_MAX 600000
#define NPB 32         // nodes per block in the GEMM kernel
#define LN_EPS 1e-5f
#define SCAN_T 1024

// Scratch (device globals; allocation-free per harness rules)
__device__ float g_agg[(size_t)N_MAX * D];
__device__ int   g_deg[N_MAX];
__device__ int   g_rowptr[N_MAX + 1];
__device__ int   g_cursor[N_MAX];
__device__ int   g_col[E_MAX];

// ---------------------------------------------------------------------------
// Kernel 0: deg = 0  (must run every launch; graph replays reuse memory)
// ---------------------------------------------------------------------------
__global__ void k_zero_deg(int N) {
    int i = blockIdx.x * blockDim.x + threadIdx.x;
    if (i < N) g_deg[i] = 0;
}

// ---------------------------------------------------------------------------
// Kernel 1: histogram of dst
// ---------------------------------------------------------------------------
__global__ void k_hist(const int* __restrict__ dst, int E) {
    int i = blockIdx.x * blockDim.x + threadIdx.x;
    if (i < E) atomicAdd(&g_deg[dst[i]], 1);
}

// ---------------------------------------------------------------------------
// Kernel 2: exclusive prefix scan over deg -> row_ptr, cursor  (single block)
// ---------------------------------------------------------------------------
__global__ __launch_bounds__(SCAN_T)
void k_scan(int N) {
    __shared__ int part[SCAN_T];
    const int t = threadIdx.x;
    const int per = (N + SCAN_T - 1) / SCAN_T;
    const int begin = t * per;
    int end = begin + per; if (end > N) end = N;

    int s = 0;
    for (int i = begin; i < end; i++) s += g_deg[i];
    part[t] = s;
    __syncthreads();

    // Hillis-Steele inclusive scan over the 1024 partials
    for (int off = 1; off < SCAN_T; off <<= 1) {
        int v = (t >= off) ? part[t - off] : 0;
        __syncthreads();
        part[t] += v;
        __syncthreads();
    }

    int run = part[t] - s;    // exclusive base for this thread's chunk
    for (int i = begin; i < end; i++) {
        g_rowptr[i] = run;
        g_cursor[i] = run;
        run += g_deg[i];
    }
    if (t == SCAN_T - 1) g_rowptr[N] = part[SCAN_T - 1];
}

// ---------------------------------------------------------------------------
// Kernel 3: bucket fill  col[cursor[dst[e]]++] = src[e]
// ---------------------------------------------------------------------------
__global__ void k_fill(const int* __restrict__ src,
                       const int* __restrict__ dst, int E) {
    int i = blockIdx.x * blockDim.x + threadIdx.x;
    if (i < E) {
        int p = atomicAdd(&g_cursor[dst[i]], 1);
        g_col[p] = src[i];
    }
}

// ---------------------------------------------------------------------------
// Kernel 4: gather-aggregate  agg[n] = h[n] + sum_{j in row n} h[col[j]]
// One warp per node; lane owns float4 columns [4l, 4l+4).
// ---------------------------------------------------------------------------
__global__ __launch_bounds__(256)
void k_gather(const float4* __restrict__ h4, int N) {
    int wid  = (blockIdx.x * blockDim.x + threadIdx.x) >> 5;
    int lane = threadIdx.x & 31;
    if (wid >= N) return;

    int start = g_rowptr[wid];
    int end   = g_rowptr[wid + 1];

    float4 acc = h4[(size_t)wid * D4 + lane];   // residual

    int j = start;
    // unroll-by-2 for a bit of MLP on the dependent col->h chain
    for (; j + 1 < end; j += 2) {
        int s0 = g_col[j];
        int s1 = g_col[j + 1];
        float4 v0 = h4[(size_t)s0 * D4 + lane];
        float4 v1 = h4[(size_t)s1 * D4 + lane];
        acc.x += v0.x + v1.x;
        acc.y += v0.y + v1.y;
        acc.z += v0.z + v1.z;
        acc.w += v0.w + v1.w;
    }
    if (j < end) {
        int s0 = g_col[j];
        float4 v0 = h4[(size_t)s0 * D4 + lane];
        acc.x += v0.x; acc.y += v0.y; acc.z += v0.z; acc.w += v0.w;
    }

    reinterpret_cast<float4*>(g_agg)[(size_t)wid * D4 + lane] = acc;
}

// ---------------------------------------------------------------------------
// Kernel 5: fused  y = agg @ W^T + b ; LayerNorm ; ReLU
// ---------------------------------------------------------------------------
__global__ __launch_bounds__(128)
void k_gemm_ln_relu(const float* __restrict__ W,
                    const float* __restrict__ bias,
                    const float* __restrict__ gamma,
                    const float* __restrict__ beta,
                    float* __restrict__ out,
                    int N) {
    __shared__ float4 xs[NPB][D4];
    __shared__ float red_s[NPB][4];
    __shared__ float red_q[NPB][4];

    const int j = threadIdx.x;          // output column 0..127
    const int lane = j & 31;
    const int warp = j >> 5;
    const int base = blockIdx.x * NPB;

    float4 w[D4];
    const float4* W4 = reinterpret_cast<const float4*>(W);
#pragma unroll
    for (int k = 0; k < D4; k++) w[k] = W4[j * D4 + k];

    const float bj  = bias[j];
    const float gj  = gamma[j];
    const float bej = beta[j];

    const float4* X4 = reinterpret_cast<const float4*>(g_agg) + (size_t)base * D4;
    int valid_rows = N - base;
    if (valid_rows > NPB) valid_rows = NPB;
    for (int i = threadIdx.x; i < NPB * D4; i += 128) {
        int r = i / D4;
        xs[r][i % D4] = (r < valid_rows) ? X4[i] : make_float4(0.f, 0.f, 0.f, 0.f);
    }
    __syncthreads();

    for (int n = 0; n < NPB; n++) {
        float y0 = 0.f, y1 = 0.f, y2 = 0.f, y3 = 0.f;
#pragma unroll
        for (int k = 0; k < D4; k++) {
            float4 x4 = xs[n][k];
            y0 += x4.x * w[k].x;
            y1 += x4.y * w[k].y;
            y2 += x4.z * w[k].z;
            y3 += x4.w * w[k].w;
        }
        float y = ((y0 + y1) + (y2 + y3)) + bj;

        float s = y, q = y * y;
#pragma unroll
        for (int o = 16; o > 0; o >>= 1) {
            s += __shfl_xor_sync(0xFFFFFFFFu, s, o);
            q += __shfl_xor_sync(0xFFFFFFFFu, q, o);
        }
        if (lane == 0) { red_s[n][warp] = s; red_q[n][warp] = q; }
        __syncthreads();

        float S = (red_s[n][0] + red_s[n][1]) + (red_s[n][2] + red_s[n][3]);
        float Q = (red_q[n][0] + red_q[n][1]) + (red_q[n][2] + red_q[n][3]);
        float mu  = S * (1.0f / D);
        float var = Q * (1.0f / D) - mu * mu;
        float rs  = rsqrtf(var + LN_EPS);
        float o   = fmaxf((y - mu) * rs * gj + bej, 0.f);

        if (base + n < N) out[(size_t)(base + n) * D + j] = o;
        __syncthreads();   // protect red_s/red_q reuse next iteration
    }
}

// ---------------------------------------------------------------------------
extern "C" void kernel_launch(void* const* d_in, const int* in_sizes, int n_in,
                              void* d_out, int out_size) {
    const float* h     = (const float*)d_in[0];
    const int*   ei    = (const int*)d_in[1];   // [2, E] int32
    const float* W     = (const float*)d_in[2];
    const float* bias  = (const float*)d_in[3];
    const float* gamma = (const float*)d_in[4];
    const float* beta  = (const float*)d_in[5];
    float*       out   = (float*)d_out;

    const int N = in_sizes[0] / D;
    const int E = in_sizes[1] / 2;
    const int* src = ei;
    const int* dst = ei + E;

    k_zero_deg<<<(N + 255) / 256, 256>>>(N);
    k_hist<<<(E + 255) / 256, 256>>>(dst, E);
    k_scan<<<1, SCAN_T>>>(N);
    k_fill<<<(E + 255) / 256, 256>>>(src, dst, E);
    k_gather<<<(N * 32 + 255) / 256, 256>>>(reinterpret_cast<const float4*>(h), N);
    k_gemm_ln_relu<<<(N + NPB - 1) / NPB, 128>>>(W, bias, gamma, beta, out, N);
}

// round 4
// speedup vs baseline: 1.4917x; 1.2265x over previous
#include <cuda_runtime.h>
#include <cstdint>

#define D 128
#define D4 32          // D / 4
#define N_MAX 50000
#define E_MAX 600000
#define NPB 32         // nodes per tile in the GEMM kernel
#define LN_EPS 1e-5f
#define SCAN_T 1024
#define GEMM_BLOCKS 296   // 2 per SM (148 SMs)

// Scratch (device globals; allocation-free per harness rules)
__device__ float g_agg[(size_t)N_MAX * D];
__device__ int   g_deg[N_MAX];
__device__ int   g_rowptr[N_MAX + 1];
__device__ int   g_cursor[N_MAX];
__device__ int   g_col[E_MAX];

// ---------------------------------------------------------------------------
// Kernel 0: deg = 0  (must run every launch; graph replays reuse memory)
// ---------------------------------------------------------------------------
__global__ void k_zero_deg(int N) {
    int i = blockIdx.x * blockDim.x + threadIdx.x;
    if (i < N) g_deg[i] = 0;
}

// ---------------------------------------------------------------------------
// Kernel 1: histogram of dst
// ---------------------------------------------------------------------------
__global__ void k_hist(const int* __restrict__ dst, int E) {
    int i = blockIdx.x * blockDim.x + threadIdx.x;
    if (i < E) atomicAdd(&g_deg[dst[i]], 1);
}

// ---------------------------------------------------------------------------
// Kernel 2: exclusive prefix scan over deg -> row_ptr, cursor  (single block)
// ---------------------------------------------------------------------------
__global__ __launch_bounds__(SCAN_T)
void k_scan(int N) {
    __shared__ int part[SCAN_T];
    const int t = threadIdx.x;
    const int per = (N + SCAN_T - 1) / SCAN_T;
    const int begin = t * per;
    int end = begin + per; if (end > N) end = N;

    int s = 0;
    for (int i = begin; i < end; i++) s += g_deg[i];
    part[t] = s;
    __syncthreads();

    for (int off = 1; off < SCAN_T; off <<= 1) {
        int v = (t >= off) ? part[t - off] : 0;
        __syncthreads();
        part[t] += v;
        __syncthreads();
    }

    int run = part[t] - s;    // exclusive base for this thread's chunk
    for (int i = begin; i < end; i++) {
        g_rowptr[i] = run;
        g_cursor[i] = run;
        run += g_deg[i];      // second read hits L1
    }
    if (t == SCAN_T - 1) g_rowptr[N] = part[SCAN_T - 1];
}

// ---------------------------------------------------------------------------
// Kernel 3: bucket fill  col[cursor[dst[e]]++] = src[e]
// ---------------------------------------------------------------------------
__global__ void k_fill(const int* __restrict__ src,
                       const int* __restrict__ dst, int E) {
    int i = blockIdx.x * blockDim.x + threadIdx.x;
    if (i < E) {
        int p = atomicAdd(&g_cursor[dst[i]], 1);
        g_col[p] = src[i];
    }
}

// ---------------------------------------------------------------------------
// Kernel 4: gather-aggregate  agg[n] = h[n] + sum_{j in row n} h[col[j]]
// One warp per node; lane owns float4 columns [4l, 4l+4). Unroll 4 for MLP.
// ---------------------------------------------------------------------------
__global__ __launch_bounds__(256)
void k_gather(const float4* __restrict__ h4, int N) {
    int wid  = (blockIdx.x * blockDim.x + threadIdx.x) >> 5;
    int lane = threadIdx.x & 31;
    if (wid >= N) return;

    int start = g_rowptr[wid];
    int end   = g_rowptr[wid + 1];

    float4 acc = h4[(size_t)wid * D4 + lane];   // residual

    int j = start;
    for (; j + 3 < end; j += 4) {
        int s0 = g_col[j], s1 = g_col[j + 1], s2 = g_col[j + 2], s3 = g_col[j + 3];
        float4 v0 = h4[(size_t)s0 * D4 + lane];
        float4 v1 = h4[(size_t)s1 * D4 + lane];
        float4 v2 = h4[(size_t)s2 * D4 + lane];
        float4 v3 = h4[(size_t)s3 * D4 + lane];
        acc.x += (v0.x + v1.x) + (v2.x + v3.x);
        acc.y += (v0.y + v1.y) + (v2.y + v3.y);
        acc.z += (v0.z + v1.z) + (v2.z + v3.z);
        acc.w += (v0.w + v1.w) + (v2.w + v3.w);
    }
    for (; j < end; j++) {
        int s0 = g_col[j];
        float4 v0 = h4[(size_t)s0 * D4 + lane];
        acc.x += v0.x; acc.y += v0.y; acc.z += v0.z; acc.w += v0.w;
    }

    reinterpret_cast<float4*>(g_agg)[(size_t)wid * D4 + lane] = acc;
}

// ---------------------------------------------------------------------------
// Kernel 5: fused  y = agg @ W^T + b ; LayerNorm ; ReLU
// Persistent blocks. Thread j owns output column j; W row j in 128 regs as
// packed f32x2 pairs. Inner loop uses fma.rn.f32x2 (FFMA2 — 2 MACs/instr).
// LN done batched after the whole tile: warp-per-node shuffle reduce.
// ---------------------------------------------------------------------------
__global__ __launch_bounds__(128, 2)
void k_gemm_ln_relu(const float* __restrict__ W,
                    const float* __restrict__ bias,
                    const float* __restrict__ gamma,
                    const float* __restrict__ beta,
                    float* __restrict__ out,
                    int N) {
    __shared__ float4 xs[NPB][D4];     // input tile
    __shared__ float  ys[NPB][D];      // pre-LN outputs

    const int j    = threadIdx.x;      // output column 0..127
    const int lane = j & 31;
    const int warp = j >> 5;

    // W row j as 32 x ulonglong2 (each .x/.y is a packed f32x2)
    ulonglong2 w[D4];
    const ulonglong2* W2 = reinterpret_cast<const ulonglong2*>(W);
#pragma unroll
    for (int k = 0; k < D4; k++) w[k] = W2[j * D4 + k];

    const float bj = bias[j];
    const float4 g4  = reinterpret_cast<const float4*>(gamma)[lane];
    const float4 be4 = reinterpret_cast<const float4*>(beta)[lane];

    const int numTiles = (N + NPB - 1) / NPB;
    for (int tile = blockIdx.x; tile < numTiles; tile += gridDim.x) {
        const int base  = tile * NPB;
        int valid = N - base; if (valid > NPB) valid = NPB;

        // Stage tile into shared
        const float4* X4 = reinterpret_cast<const float4*>(g_agg) + (size_t)base * D4;
        for (int i = j; i < NPB * D4; i += 128) {
            int r = i >> 5;
            xs[r][i & 31] = (r < valid) ? X4[i] : make_float4(0.f, 0.f, 0.f, 0.f);
        }
        __syncthreads();

        // Compute y for every node in the tile (no syncs inside)
        for (int n = 0; n < NPB; n++) {
            // 4 independent packed accumulator chains
            unsigned long long a01a = 0ull, a23a = 0ull, a01b = 0ull, a23b = 0ull;
            const ulonglong2* xrow = reinterpret_cast<const ulonglong2*>(xs[n]);
#pragma unroll
            for (int k = 0; k < D4; k += 2) {
                ulonglong2 x0 = xrow[k];
                ulonglong2 x1 = xrow[k + 1];
                asm("fma.rn.f32x2 %0, %1, %2, %0;" : "+l"(a01a) : "l"(x0.x), "l"(w[k].x));
                asm("fma.rn.f32x2 %0, %1, %2, %0;" : "+l"(a23a) : "l"(x0.y), "l"(w[k].y));
                asm("fma.rn.f32x2 %0, %1, %2, %0;" : "+l"(a01b) : "l"(x1.x), "l"(w[k + 1].x));
                asm("fma.rn.f32x2 %0, %1, %2, %0;" : "+l"(a23b) : "l"(x1.y), "l"(w[k + 1].y));
            }
            unsigned int l0, h0, l1, h1, l2, h2, l3, h3;
            asm("mov.b64 {%0, %1}, %2;" : "=r"(l0), "=r"(h0) : "l"(a01a));
            asm("mov.b64 {%0, %1}, %2;" : "=r"(l1), "=r"(h1) : "l"(a23a));
            asm("mov.b64 {%0, %1}, %2;" : "=r"(l2), "=r"(h2) : "l"(a01b));
            asm("mov.b64 {%0, %1}, %2;" : "=r"(l3), "=r"(h3) : "l"(a23b));
            float y = ((__uint_as_float(l0) + __uint_as_float(h0)) +
                       (__uint_as_float(l1) + __uint_as_float(h1))) +
                      ((__uint_as_float(l2) + __uint_as_float(h2)) +
                       (__uint_as_float(l3) + __uint_as_float(h3))) + bj;
            ys[n][j] = y;
        }
        __syncthreads();

        // Batched LN + ReLU: warp handles nodes warp, warp+4, ...
        for (int n = warp; n < valid; n += 4) {
            float4 v = reinterpret_cast<const float4*>(ys[n])[lane];
            float s = (v.x + v.y) + (v.z + v.w);
            float q = (v.x * v.x + v.y * v.y) + (v.z * v.z + v.w * v.w);
#pragma unroll
            for (int o = 16; o > 0; o >>= 1) {
                s += __shfl_xor_sync(0xFFFFFFFFu, s, o);
                q += __shfl_xor_sync(0xFFFFFFFFu, q, o);
            }
            float mu  = s * (1.0f / D);
            float var = q * (1.0f / D) - mu * mu;
            float rs  = rsqrtf(var + LN_EPS);
            float4 o4;
            o4.x = fmaxf((v.x - mu) * rs * g4.x + be4.x, 0.f);
            o4.y = fmaxf((v.y - mu) * rs * g4.y + be4.y, 0.f);
            o4.z = fmaxf((v.z - mu) * rs * g4.z + be4.z, 0.f);
            o4.w = fmaxf((v.w - mu) * rs * g4.w + be4.w, 0.f);
            reinterpret_cast<float4*>(out + (size_t)(base + n) * D)[lane] = o4;
        }
        __syncthreads();   // xs/ys reused next tile
    }
}

// ---------------------------------------------------------------------------
extern "C" void kernel_launch(void* const* d_in, const int* in_sizes, int n_in,
                              void* d_out, int out_size) {
    const float* h     = (const float*)d_in[0];
    const int*   ei    = (const int*)d_in[1];   // [2, E] int32
    const float* W     = (const float*)d_in[2];
    const float* bias  = (const float*)d_in[3];
    const float* gamma = (const float*)d_in[4];
    const float* beta  = (const float*)d_in[5];
    float*       out   = (float*)d_out;

    const int N = in_sizes[0] / D;
    const int E = in_sizes[1] / 2;
    const int* src = ei;
    const int* dst = ei + E;

    k_zero_deg<<<(N + 255) / 256, 256>>>(N);
    k_hist<<<(E + 255) / 256, 256>>>(dst, E);
    k_scan<<<1, SCAN_T>>>(N);
    k_fill<<<(E + 255) / 256, 256>>>(src, dst, E);
    k_gather<<<(N * 32 + 255) / 256, 256>>>(reinterpret_cast<const float4*>(h), N);
    k_gemm_ln_relu<<<GEMM_BLOCKS, 128>>>(W, bias, gamma, beta, out, N);
}